// round 10
// baseline (speedup 1.0000x reference)
#include <cuda_runtime.h>
#include <cuda_fp16.h>
#include <math.h>
#include <math_constants.h>
#include <cstdint>

#define T_TOK 2048
#define H_DIM 1024
#define F_DIM 4096
#define E_NUM 8
#define MAXPAIRS (2 * T_TOK)

// ================= scratch (__device__ globals; no runtime alloc) =================
__device__ float  g_logits[T_TOK * E_NUM];
__device__ int    g_cnt[E_NUM];
__device__ int    g_off[E_NUM];
__device__ int    g_tok[MAXPAIRS];
__device__ float  g_coef[MAXPAIRS];
__device__ __align__(16) __half g_xh[T_TOK * H_DIM];                 // x in fp16
__device__ __align__(16) __half g_h16[(size_t)MAXPAIRS * F_DIM];     // intermediate, fp16

// ================= helpers =================
__device__ __forceinline__ uint32_t smem_u32(const void* p) {
    uint32_t a;
    asm("{ .reg .u64 t; cvta.to.shared.u64 t, %1; cvt.u32.u64 %0, t; }" : "=r"(a) : "l"(p));
    return a;
}
__device__ __forceinline__ uint32_t h2u(float a, float b) {
    __half2 h = __floats2half2_rn(a, b);
    return *reinterpret_cast<uint32_t*>(&h);
}
#define CPA(dst, src) \
    asm volatile("cp.async.cg.shared.global [%0], [%1], 16;" ::"r"(dst), "l"(src) : "memory")
#define CPA_COMMIT() asm volatile("cp.async.commit_group;" ::: "memory")
#define CPA_WAIT1()  asm volatile("cp.async.wait_group 1;" ::: "memory")
#define CPA_WAIT0()  asm volatile("cp.async.wait_group 0;" ::: "memory")
#define MMA_F16(d, a, b0, b1)                                                            \
    asm volatile(                                                                        \
        "mma.sync.aligned.m16n8k16.row.col.f32.f16.f16.f32 "                             \
        "{%0,%1,%2,%3},{%4,%5,%6,%7},{%8,%9},{%0,%1,%2,%3};"                             \
        : "+f"((d)[0]), "+f"((d)[1]), "+f"((d)[2]), "+f"((d)[3])                         \
        : "r"((a)[0]), "r"((a)[1]), "r"((a)[2]), "r"((a)[3]), "r"(b0), "r"(b1))

// transpose-convert one 32k x 128n fp32 chunk (raw[k][n], row=128 floats) into
// fp16 [n][k] tile with row stride 20 words. 512 threads. Bank-conflict-free.
__device__ __forceinline__ void cvt_tile(const float* __restrict__ raw,
                                         uint32_t* __restrict__ conv, int tid) {
    const int n = tid & 127, kg = tid >> 7;          // kg in 0..3, 8 k's each
    const float* src = raw + kg * 8 * 128 + n;
    float f0 = src[0],       f1 = src[128],     f2 = src[2 * 128], f3 = src[3 * 128];
    float f4 = src[4 * 128], f5 = src[5 * 128], f6 = src[6 * 128], f7 = src[7 * 128];
    uint4 p;
    p.x = h2u(f0, f1); p.y = h2u(f2, f3); p.z = h2u(f4, f5); p.w = h2u(f6, f7);
    *(uint4*)(conv + n * 20 + kg * 4) = p;
}

// ================= K0: router logits + zero output rows + x->fp16 =================
__global__ __launch_bounds__(256) void router_kernel(
    const float* __restrict__ x, const float* __restrict__ gw,
    float* __restrict__ out, float* __restrict__ out_logits) {
    __shared__ float sgw[E_NUM * H_DIM];
    for (int i = threadIdx.x; i < H_DIM * E_NUM; i += 256) {
        int h = i >> 3, e = i & 7;
        sgw[e * H_DIM + h] = gw[i];
    }
    {
        float4 z = make_float4(0.f, 0.f, 0.f, 0.f);
        float4* dst = (float4*)(out + (size_t)blockIdx.x * 8 * H_DIM);
#pragma unroll
        for (int i = 0; i < 8; i++) dst[threadIdx.x + i * 256] = z;
    }
    {
        const float4* src = (const float4*)(x + (size_t)blockIdx.x * 8 * H_DIM);
        __half2* dst = (__half2*)(g_xh + (size_t)blockIdx.x * 8 * H_DIM);
#pragma unroll
        for (int i = 0; i < 8; i++) {
            float4 v = src[threadIdx.x + i * 256];
            dst[(threadIdx.x + i * 256) * 2 + 0] = __floats2half2_rn(v.x, v.y);
            dst[(threadIdx.x + i * 256) * 2 + 1] = __floats2half2_rn(v.z, v.w);
        }
    }
    __syncthreads();
    int warp = threadIdx.x >> 5, lane = threadIdx.x & 31;
    int t = blockIdx.x * 8 + warp;
    const float* xr = x + (size_t)t * H_DIM;
    float acc[E_NUM];
#pragma unroll
    for (int e = 0; e < E_NUM; e++) acc[e] = 0.0f;
    for (int h = lane; h < H_DIM; h += 32) {
        float xv = xr[h];
#pragma unroll
        for (int e = 0; e < E_NUM; e++) acc[e] += xv * sgw[e * H_DIM + h];
    }
#pragma unroll
    for (int e = 0; e < E_NUM; e++) {
#pragma unroll
        for (int o = 16; o > 0; o >>= 1) acc[e] += __shfl_down_sync(0xffffffffu, acc[e], o);
    }
    if (lane == 0) {
#pragma unroll
        for (int e = 0; e < E_NUM; e++) {
            g_logits[t * E_NUM + e] = acc[e];
            out_logits[t * E_NUM + e] = acc[e];
        }
    }
}

// ================= K1: routing + count + prefix + scatter (single CTA) =================
__global__ __launch_bounds__(1024) void route_scatter_kernel() {
    __shared__ int s_cnt[E_NUM];
    __shared__ int s_cur[E_NUM];
    const int tid = threadIdx.x;
    if (tid < E_NUM) s_cnt[tid] = 0;
    __syncthreads();
    int ti0[2], ti1[2];
    float tc0[2], tc1[2];
#pragma unroll
    for (int q = 0; q < 2; q++) {
        int t = tid + q * 1024;
        float s[E_NUM];
#pragma unroll
        for (int e = 0; e < E_NUM; e++) s[e] = g_logits[t * E_NUM + e];
        float mx = s[0];
        int i0 = 0;
#pragma unroll
        for (int e = 1; e < E_NUM; e++)
            if (s[e] > mx) { mx = s[e]; i0 = e; }
        float denom = 0.0f;
#pragma unroll
        for (int e = 0; e < E_NUM; e++) {
            float f = fmaxf(fabsf(s[e]), mx);
            if (!((mx - s[e]) / f > 0.02f)) denom += expf(s[e] - mx);
        }
        float w0 = 1.0f / denom;
        float mx2 = -CUDART_INF_F;
        int i1 = 0;
#pragma unroll
        for (int e = 0; e < E_NUM; e++)
            if (e != i0 && s[e] > mx2) { mx2 = s[e]; i1 = e; }
        float denom2 = 0.0f;
#pragma unroll
        for (int e = 0; e < E_NUM; e++) {
            if (e == i0) continue;
            float f = fmaxf(fabsf(s[e]), mx2);
            if (!((mx2 - s[e]) / f > 0.02f)) denom2 += expf(s[e] - mx2);
        }
        float w1v = 1.0f / denom2;
        float c0 = (i0 == 0) ? w0 : ((i1 == 0) ? w1v : 0.0f);
        float c1 = (i0 == 1) ? w0 : ((i1 == 1) ? w1v : 0.0f);
        ti0[q] = i0; tc0[q] = c0;
        ti1[q] = i1; tc1[q] = c1;
        if (c0 != 0.0f) atomicAdd(&s_cnt[i0], 1);
        if (c1 != 0.0f) atomicAdd(&s_cnt[i1], 1);
    }
    __syncthreads();
    if (tid == 0) {
        int acc = 0;
        for (int e = 0; e < E_NUM; e++) {
            g_off[e] = acc;
            s_cur[e] = acc;
            g_cnt[e] = s_cnt[e];
            acc += s_cnt[e];
        }
    }
    __syncthreads();
#pragma unroll
    for (int q = 0; q < 2; q++) {
        int t = tid + q * 1024;
        if (tc0[q] != 0.0f) {
            int slot = atomicAdd(&s_cur[ti0[q]], 1);
            g_tok[slot] = t; g_coef[slot] = tc0[q];
        }
        if (tc1[q] != 0.0f) {
            int slot = atomicAdd(&s_cur[ti1[q]], 1);
            g_tok[slot] = t; g_coef[slot] = tc1[q];
        }
    }
}

// ================= smem layouts (3-stage pipeline) =================
#define TW 20
// per-stage sizes: A = 10240 B, raw = 16384 B; CV (single) = 10240 B
// gemm1 (A + CV1 + CV3 + R1 + R3)
#define G1_TOK   0
#define G1_SA    512
#define G1_CV1   (G1_SA + 3 * 10240)      // 31232
#define G1_CV3   (G1_CV1 + 10240)         // 41472
#define G1_R1    (G1_CV3 + 10240)         // 51712
#define G1_R3    (G1_R1 + 3 * 16384)      // 100864
#define G1_SMEM  (G1_R3 + 3 * 16384)      // 150016
// gemm2 (A + CV + R)
#define G2_ROW   0
#define G2_SA    512
#define G2_CV    (G2_SA + 3 * 10240)      // 31232
#define G2_R     (G2_CV + 10240)          // 41472
#define G2_SMEM  (G2_R + 3 * 16384)       // 90624

// ================= GEMM1: h = silu(Xe@W1) * (Xe@W3) =================
// tile M=128, N=128, Kc=32; 512 threads (4x4 warps, 32x32 warp tiles).
// 3-stage cp.async pipeline, 2-chunk prefetch, 2 syncs/chunk.
__global__ __launch_bounds__(512) void gemm1_kernel(
    const float* __restrict__ w1, const float* __restrict__ w3) {
    const int e = blockIdx.z;
    const int cnt = g_cnt[e];
    const int m0 = blockIdx.y * 128;
    if (m0 >= cnt) return;
    const int off = g_off[e];
    const int n0 = blockIdx.x * 128;
    const float* __restrict__ W1 = w1 + (size_t)e * H_DIM * F_DIM;
    const float* __restrict__ W3 = w3 + (size_t)e * H_DIM * F_DIM;

    extern __shared__ char sm[];
    int* stok = (int*)(sm + G1_TOK);
    uint32_t* SA  = (uint32_t*)(sm + G1_SA);
    uint32_t* CV1 = (uint32_t*)(sm + G1_CV1);
    uint32_t* CV3 = (uint32_t*)(sm + G1_CV3);
    float* R1 = (float*)(sm + G1_R1);
    float* R3 = (float*)(sm + G1_R3);

    const int tid = threadIdx.x, wid = tid >> 5, lane = tid & 31;
    const int gid = lane >> 2, tg = lane & 3;
    const int wm = wid >> 2, wn = wid & 3;

    if (tid < 128) {
        int r = m0 + tid;
        stok[tid] = g_tok[off + (r < cnt ? r : cnt - 1)];
    }
    __syncthreads();

    const int lrow = tid >> 2, lc = tid & 3;
    const __half* asrc = g_xh + (size_t)stok[lrow] * H_DIM + lc * 8;
    const uint32_t adst = (uint32_t)(lrow * 80 + lc * 16);
    const int kk0 = tid >> 5, nc0 = tid & 31;
    const int kk1 = (tid + 512) >> 5, nc1 = tid & 31;
    const float* b1s0 = W1 + (size_t)kk0 * F_DIM + n0 + nc0 * 4;
    const float* b1s1 = W1 + (size_t)kk1 * F_DIM + n0 + nc1 * 4;
    const float* b3s0 = W3 + (size_t)kk0 * F_DIM + n0 + nc0 * 4;
    const float* b3s1 = W3 + (size_t)kk1 * F_DIM + n0 + nc1 * 4;
    const uint32_t bd0 = (uint32_t)((kk0 * 128 + nc0 * 4) * 4);
    const uint32_t bd1 = (uint32_t)((kk1 * 128 + nc1 * 4) * 4);
    const uint32_t Ab = smem_u32(SA), R1b = smem_u32(R1), R3b = smem_u32(R3);

    float acc1[2][4][4] = {};
    float acc3[2][4][4] = {};

#define G1_ISSUE(c)                                         \
    do {                                                    \
        uint32_t _s = (uint32_t)((c) % 3);                  \
        uint32_t _ao = _s * 10240u;                         \
        uint32_t _ro = _s * 16384u;                         \
        size_t _ka = (size_t)(c) * 32;                      \
        size_t _kb = (size_t)(c) * 32 * F_DIM;              \
        CPA(Ab + _ao + adst, asrc + _ka);                   \
        CPA(R1b + _ro + bd0, b1s0 + _kb);                   \
        CPA(R1b + _ro + bd1, b1s1 + _kb);                   \
        CPA(R3b + _ro + bd0, b3s0 + _kb);                   \
        CPA(R3b + _ro + bd1, b3s1 + _kb);                   \
        CPA_COMMIT();                                       \
    } while (0)

    G1_ISSUE(0);
    G1_ISSUE(1);
    for (int c = 0; c < 32; c++) {
        const int s = c % 3;
        if (c + 1 < 32) CPA_WAIT1();     // group c done; group c+1 in flight
        else CPA_WAIT0();
        __syncthreads();                 // publish A(c)/raw(c); prior readers done
        if (c + 2 < 32) G1_ISSUE(c + 2); // post-sync: stage (c+2)%3 is free
        cvt_tile(R1 + s * 4096, CV1, tid);
        cvt_tile(R3 + s * 4096, CV3, tid);
        __syncthreads();                 // CV(c) visible
        const uint32_t* A = SA + s * 2560;
#pragma unroll
        for (int ks = 0; ks < 2; ks++) {
            uint32_t a[2][4];
#pragma unroll
            for (int mt = 0; mt < 2; mt++) {
                int rb = (wm * 32 + mt * 16 + gid) * TW + tg + ks * 8;
                a[mt][0] = A[rb];
                a[mt][1] = A[rb + 8 * TW];
                a[mt][2] = A[rb + 4];
                a[mt][3] = A[rb + 8 * TW + 4];
            }
#pragma unroll
            for (int nt = 0; nt < 4; nt++) {
                int bb = (wn * 32 + nt * 8 + gid) * TW + tg + ks * 8;
                uint32_t b10 = CV1[bb], b11 = CV1[bb + 4];
                uint32_t b30 = CV3[bb], b31 = CV3[bb + 4];
#pragma unroll
                for (int mt = 0; mt < 2; mt++) {
                    MMA_F16(acc1[mt][nt], a[mt], b10, b11);
                    MMA_F16(acc3[mt][nt], a[mt], b30, b31);
                }
            }
        }
        // no end sync: next iter's top sync orders MMA(c) reads vs cvt(c+1) writes
    }

    // epilogue: silu(acc1)*acc3 -> g_h16 (fp16)
#pragma unroll
    for (int mt = 0; mt < 2; mt++) {
#pragma unroll
        for (int half = 0; half < 2; half++) {
            int row = m0 + wm * 32 + mt * 16 + half * 8 + gid;
            if (row < cnt) {
                __half* hp = g_h16 + (size_t)(off + row) * F_DIM + n0 + wn * 32 + tg * 2;
#pragma unroll
                for (int nt = 0; nt < 4; nt++) {
                    float g0 = acc1[mt][nt][half * 2 + 0];
                    float g1 = acc1[mt][nt][half * 2 + 1];
                    float u0 = acc3[mt][nt][half * 2 + 0];
                    float u1 = acc3[mt][nt][half * 2 + 1];
                    float o0 = u0 * (g0 / (1.0f + expf(-g0)));
                    float o1 = u1 * (g1 / (1.0f + expf(-g1)));
                    *(__half2*)(hp + nt * 8) = __floats2half2_rn(o0, o1);
                }
            }
        }
    }
}

// ================= GEMM2: out += coef * (h @ W2)  (split-K 4) =================
// tile M=128, N=128, Kc=32; 512 threads; 3-stage pipeline; 2 CTAs/SM via reg cap.
__global__ __launch_bounds__(512, 2) void gemm2_kernel(
    const float* __restrict__ w2, float* __restrict__ out) {
    const int z = blockIdx.z;
    const int e = z >> 2, ks4 = z & 3;
    const int cnt = g_cnt[e];
    const int m0 = blockIdx.y * 128;
    if (m0 >= cnt) return;
    const int off = g_off[e];
    const int n0 = blockIdx.x * 128;
    const int kbase = ks4 * (F_DIM / 4);
    const float* __restrict__ W2 = w2 + (size_t)e * F_DIM * H_DIM;

    extern __shared__ char sm[];
    int* srow = (int*)(sm + G2_ROW);
    uint32_t* SA = (uint32_t*)(sm + G2_SA);
    uint32_t* CV = (uint32_t*)(sm + G2_CV);
    float* RB = (float*)(sm + G2_R);

    const int tid = threadIdx.x, wid = tid >> 5, lane = tid & 31;
    const int gid = lane >> 2, tg = lane & 3;
    const int wm = wid >> 2, wn = wid & 3;

    if (tid < 128) {
        int r = m0 + tid;
        srow[tid] = off + (r < cnt ? r : cnt - 1);
    }
    __syncthreads();

    const int lrow = tid >> 2, lc = tid & 3;
    const __half* asrc = g_h16 + (size_t)srow[lrow] * F_DIM + kbase + lc * 8;
    const uint32_t adst = (uint32_t)(lrow * 80 + lc * 16);
    const int kk0 = tid >> 5, nc0 = tid & 31;
    const int kk1 = (tid + 512) >> 5, nc1 = tid & 31;
    const float* bs0 = W2 + (size_t)(kbase + kk0) * H_DIM + n0 + nc0 * 4;
    const float* bs1 = W2 + (size_t)(kbase + kk1) * H_DIM + n0 + nc1 * 4;
    const uint32_t bd0 = (uint32_t)((kk0 * 128 + nc0 * 4) * 4);
    const uint32_t bd1 = (uint32_t)((kk1 * 128 + nc1 * 4) * 4);
    const uint32_t Ab = smem_u32(SA), Rb = smem_u32(RB);

    float acc[2][4][4] = {};

#define G2_ISSUE(c)                                         \
    do {                                                    \
        uint32_t _s = (uint32_t)((c) % 3);                  \
        uint32_t _ao = _s * 10240u;                         \
        uint32_t _ro = _s * 16384u;                         \
        size_t _ka = (size_t)(c) * 32;                      \
        size_t _kb = (size_t)(c) * 32 * H_DIM;              \
        CPA(Ab + _ao + adst, asrc + _ka);                   \
        CPA(Rb + _ro + bd0, bs0 + _kb);                     \
        CPA(Rb + _ro + bd1, bs1 + _kb);                     \
        CPA_COMMIT();                                       \
    } while (0)

    G2_ISSUE(0);
    G2_ISSUE(1);
    for (int c = 0; c < 32; c++) {
        const int s = c % 3;
        if (c + 1 < 32) CPA_WAIT1();
        else CPA_WAIT0();
        __syncthreads();
        if (c + 2 < 32) G2_ISSUE(c + 2);
        cvt_tile(RB + s * 4096, CV, tid);
        __syncthreads();
        const uint32_t* A = SA + s * 2560;
#pragma unroll
        for (int ks = 0; ks < 2; ks++) {
            uint32_t a[2][4];
#pragma unroll
            for (int mt = 0; mt < 2; mt++) {
                int rb = (wm * 32 + mt * 16 + gid) * TW + tg + ks * 8;
                a[mt][0] = A[rb];
                a[mt][1] = A[rb + 8 * TW];
                a[mt][2] = A[rb + 4];
                a[mt][3] = A[rb + 8 * TW + 4];
            }
#pragma unroll
            for (int nt = 0; nt < 4; nt++) {
                int bb = (wn * 32 + nt * 8 + gid) * TW + tg + ks * 8;
                uint32_t b0 = CV[bb], b1 = CV[bb + 4];
#pragma unroll
                for (int mt = 0; mt < 2; mt++) MMA_F16(acc[mt][nt], a[mt], b0, b1);
            }
        }
    }

    // epilogue: atomic scaled scatter
#pragma unroll
    for (int mt = 0; mt < 2; mt++) {
#pragma unroll
        for (int half = 0; half < 2; half++) {
            int row = m0 + wm * 32 + mt * 16 + half * 8 + gid;
            if (row < cnt) {
                int slot = off + row;
                int tok = g_tok[slot];
                float coef = g_coef[slot];
                float* dst = out + (size_t)tok * H_DIM + n0 + wn * 32 + tg * 2;
#pragma unroll
                for (int nt = 0; nt < 4; nt++) {
                    atomicAdd(dst + nt * 8 + 0, acc[mt][nt][half * 2 + 0] * coef);
                    atomicAdd(dst + nt * 8 + 1, acc[mt][nt][half * 2 + 1] * coef);
                }
            }
        }
    }
}

// ================= launch =================
extern "C" void kernel_launch(void* const* d_in, const int* in_sizes, int n_in,
                              void* d_out, int out_size) {
    const float* x  = (const float*)d_in[0];
    const float* gw = (const float*)d_in[1];
    const float* w1 = (const float*)d_in[2];
    const float* w3 = (const float*)d_in[3];
    const float* w2 = (const float*)d_in[4];
    float* out = (float*)d_out;
    float* out_logits = out + (size_t)T_TOK * H_DIM;

    cudaFuncSetAttribute(gemm1_kernel, cudaFuncAttributeMaxDynamicSharedMemorySize, G1_SMEM);
    cudaFuncSetAttribute(gemm2_kernel, cudaFuncAttributeMaxDynamicSharedMemorySize, G2_SMEM);

    router_kernel<<<T_TOK / 8, 256>>>(x, gw, out, out_logits);
    route_scatter_kernel<<<1, 1024>>>();
    gemm1_kernel<<<dim3(F_DIM / 128, T_TOK / 128, E_NUM), 512, G1_SMEM>>>(w1, w3);
    gemm2_kernel<<<dim3(H_DIM / 128, T_TOK / 128, E_NUM * 4), 512, G2_SMEM>>>(w2, out);
}

// round 11
// speedup vs baseline: 1.1003x; 1.1003x over previous
#include <cuda_runtime.h>
#include <cuda_fp16.h>
#include <math.h>
#include <math_constants.h>
#include <cstdint>

#define T_TOK 2048
#define H_DIM 1024
#define F_DIM 4096
#define E_NUM 8
#define MAXPAIRS (2 * T_TOK)

// ================= scratch (__device__ globals; no runtime alloc) =================
__device__ float  g_logits[T_TOK * E_NUM];
__device__ int    g_cnt[E_NUM];
__device__ int    g_off[E_NUM];
__device__ int    g_tok[MAXPAIRS];
__device__ float  g_coef[MAXPAIRS];
__device__ __align__(16) __half g_xh[T_TOK * H_DIM];                 // x in fp16
__device__ __align__(16) __half g_h16[(size_t)MAXPAIRS * F_DIM];     // intermediate, fp16

// ================= helpers =================
__device__ __forceinline__ uint32_t smem_u32(const void* p) {
    uint32_t a;
    asm("{ .reg .u64 t; cvta.to.shared.u64 t, %1; cvt.u32.u64 %0, t; }" : "=r"(a) : "l"(p));
    return a;
}
__device__ __forceinline__ uint32_t h2u(float a, float b) {
    __half2 h = __floats2half2_rn(a, b);
    return *reinterpret_cast<uint32_t*>(&h);
}
#define CPA(dst, src) \
    asm volatile("cp.async.cg.shared.global [%0], [%1], 16;" ::"r"(dst), "l"(src) : "memory")
#define CPA_COMMIT() asm volatile("cp.async.commit_group;" ::: "memory")
#define CPA_WAIT1()  asm volatile("cp.async.wait_group 1;" ::: "memory")
#define CPA_WAIT0()  asm volatile("cp.async.wait_group 0;" ::: "memory")
#define MMA_F16(d, a, b0, b1)                                                            \
    asm volatile(                                                                        \
        "mma.sync.aligned.m16n8k16.row.col.f32.f16.f16.f32 "                             \
        "{%0,%1,%2,%3},{%4,%5,%6,%7},{%8,%9},{%0,%1,%2,%3};"                             \
        : "+f"((d)[0]), "+f"((d)[1]), "+f"((d)[2]), "+f"((d)[3])                         \
        : "r"((a)[0]), "r"((a)[1]), "r"((a)[2]), "r"((a)[3]), "r"(b0), "r"(b1))
#define LDSM4(r, a)                                                                      \
    asm volatile("ldmatrix.sync.aligned.m8n8.x4.shared.b16 {%0,%1,%2,%3}, [%4];"          \
                 : "=r"((r)[0]), "=r"((r)[1]), "=r"((r)[2]), "=r"((r)[3]) : "r"(a))

// transpose-convert one 32k x 128n fp32 chunk (raw[k][n], row=128 floats) into
// fp16 [n][k] tile with row stride 20 words. 512 threads. Bank-conflict-free.
__device__ __forceinline__ void cvt_tile(const float* __restrict__ raw,
                                         uint32_t* __restrict__ conv, int tid) {
    const int n = tid & 127, kg = tid >> 7;          // kg in 0..3, 8 k's each
    const float* src = raw + kg * 8 * 128 + n;
    float f0 = src[0],       f1 = src[128],     f2 = src[2 * 128], f3 = src[3 * 128];
    float f4 = src[4 * 128], f5 = src[5 * 128], f6 = src[6 * 128], f7 = src[7 * 128];
    uint4 p;
    p.x = h2u(f0, f1); p.y = h2u(f2, f3); p.z = h2u(f4, f5); p.w = h2u(f6, f7);
    *(uint4*)(conv + n * 20 + kg * 4) = p;
}

// ================= K0: router logits + zero output rows + x->fp16 =================
__global__ __launch_bounds__(256) void router_kernel(
    const float* __restrict__ x, const float* __restrict__ gw,
    float* __restrict__ out, float* __restrict__ out_logits) {
    __shared__ float sgw[E_NUM * H_DIM];
    for (int i = threadIdx.x; i < H_DIM * E_NUM; i += 256) {
        int h = i >> 3, e = i & 7;
        sgw[e * H_DIM + h] = gw[i];
    }
    {
        float4 z = make_float4(0.f, 0.f, 0.f, 0.f);
        float4* dst = (float4*)(out + (size_t)blockIdx.x * 8 * H_DIM);
#pragma unroll
        for (int i = 0; i < 8; i++) dst[threadIdx.x + i * 256] = z;
    }
    {
        const float4* src = (const float4*)(x + (size_t)blockIdx.x * 8 * H_DIM);
        __half2* dst = (__half2*)(g_xh + (size_t)blockIdx.x * 8 * H_DIM);
#pragma unroll
        for (int i = 0; i < 8; i++) {
            float4 v = src[threadIdx.x + i * 256];
            dst[(threadIdx.x + i * 256) * 2 + 0] = __floats2half2_rn(v.x, v.y);
            dst[(threadIdx.x + i * 256) * 2 + 1] = __floats2half2_rn(v.z, v.w);
        }
    }
    __syncthreads();
    int warp = threadIdx.x >> 5, lane = threadIdx.x & 31;
    int t = blockIdx.x * 8 + warp;
    const float* xr = x + (size_t)t * H_DIM;
    float acc[E_NUM];
#pragma unroll
    for (int e = 0; e < E_NUM; e++) acc[e] = 0.0f;
    for (int h = lane; h < H_DIM; h += 32) {
        float xv = xr[h];
#pragma unroll
        for (int e = 0; e < E_NUM; e++) acc[e] += xv * sgw[e * H_DIM + h];
    }
#pragma unroll
    for (int e = 0; e < E_NUM; e++) {
#pragma unroll
        for (int o = 16; o > 0; o >>= 1) acc[e] += __shfl_down_sync(0xffffffffu, acc[e], o);
    }
    if (lane == 0) {
#pragma unroll
        for (int e = 0; e < E_NUM; e++) {
            g_logits[t * E_NUM + e] = acc[e];
            out_logits[t * E_NUM + e] = acc[e];
        }
    }
}

// ================= K1: routing + count + prefix + scatter (single CTA) =================
__global__ __launch_bounds__(1024) void route_scatter_kernel() {
    __shared__ int s_cnt[E_NUM];
    __shared__ int s_cur[E_NUM];
    const int tid = threadIdx.x;
    if (tid < E_NUM) s_cnt[tid] = 0;
    __syncthreads();
    int ti0[2], ti1[2];
    float tc0[2], tc1[2];
#pragma unroll
    for (int q = 0; q < 2; q++) {
        int t = tid + q * 1024;
        float s[E_NUM];
#pragma unroll
        for (int e = 0; e < E_NUM; e++) s[e] = g_logits[t * E_NUM + e];
        float mx = s[0];
        int i0 = 0;
#pragma unroll
        for (int e = 1; e < E_NUM; e++)
            if (s[e] > mx) { mx = s[e]; i0 = e; }
        float denom = 0.0f;
#pragma unroll
        for (int e = 0; e < E_NUM; e++) {
            float f = fmaxf(fabsf(s[e]), mx);
            if (!((mx - s[e]) / f > 0.02f)) denom += expf(s[e] - mx);
        }
        float w0 = 1.0f / denom;
        float mx2 = -CUDART_INF_F;
        int i1 = 0;
#pragma unroll
        for (int e = 0; e < E_NUM; e++)
            if (e != i0 && s[e] > mx2) { mx2 = s[e]; i1 = e; }
        float denom2 = 0.0f;
#pragma unroll
        for (int e = 0; e < E_NUM; e++) {
            if (e == i0) continue;
            float f = fmaxf(fabsf(s[e]), mx2);
            if (!((mx2 - s[e]) / f > 0.02f)) denom2 += expf(s[e] - mx2);
        }
        float w1v = 1.0f / denom2;
        float c0 = (i0 == 0) ? w0 : ((i1 == 0) ? w1v : 0.0f);
        float c1 = (i0 == 1) ? w0 : ((i1 == 1) ? w1v : 0.0f);
        ti0[q] = i0; tc0[q] = c0;
        ti1[q] = i1; tc1[q] = c1;
        if (c0 != 0.0f) atomicAdd(&s_cnt[i0], 1);
        if (c1 != 0.0f) atomicAdd(&s_cnt[i1], 1);
    }
    __syncthreads();
    if (tid == 0) {
        int acc = 0;
        for (int e = 0; e < E_NUM; e++) {
            g_off[e] = acc;
            s_cur[e] = acc;
            g_cnt[e] = s_cnt[e];
            acc += s_cnt[e];
        }
    }
    __syncthreads();
#pragma unroll
    for (int q = 0; q < 2; q++) {
        int t = tid + q * 1024;
        if (tc0[q] != 0.0f) {
            int slot = atomicAdd(&s_cur[ti0[q]], 1);
            g_tok[slot] = t; g_coef[slot] = tc0[q];
        }
        if (tc1[q] != 0.0f) {
            int slot = atomicAdd(&s_cur[ti1[q]], 1);
            g_tok[slot] = t; g_coef[slot] = tc1[q];
        }
    }
}

// ================= smem layouts =================
#define TW 20
// gemm1: 2-stage A/raw, single CV (round-9 structure)
#define G1_TOK   0
#define G1_SA    512
#define G1_CV1   (G1_SA + 2 * 10240)      // 20992
#define G1_CV3   (G1_CV1 + 10240)         // 31232
#define G1_R1    (G1_CV3 + 10240)         // 41472
#define G1_R3    (G1_R1 + 2 * 16384)      // 74240
#define G1_SMEM  (G1_R3 + 2 * 16384)      // 107008
// gemm2: 3-stage A/raw, single CV (round-10 structure)
#define G2_ROW   0
#define G2_SA    512
#define G2_CV    (G2_SA + 3 * 10240)      // 31232
#define G2_R     (G2_CV + 10240)          // 41472
#define G2_SMEM  (G2_R + 3 * 16384)       // 90624

// ================= GEMM1: h = silu(Xe@W1) * (Xe@W3) =================
// tile M=128, N=128, Kc=32; 512 threads (4x4 warps, 32x32 warp tiles); ldmatrix frags.
__global__ __launch_bounds__(512) void gemm1_kernel(
    const float* __restrict__ w1, const float* __restrict__ w3) {
    const int e = blockIdx.z;
    const int cnt = g_cnt[e];
    const int m0 = blockIdx.y * 128;
    if (m0 >= cnt) return;
    const int off = g_off[e];
    const int n0 = blockIdx.x * 128;
    const float* __restrict__ W1 = w1 + (size_t)e * H_DIM * F_DIM;
    const float* __restrict__ W3 = w3 + (size_t)e * H_DIM * F_DIM;

    extern __shared__ char sm[];
    int* stok = (int*)(sm + G1_TOK);
    uint32_t* CV1 = (uint32_t*)(sm + G1_CV1);
    uint32_t* CV3 = (uint32_t*)(sm + G1_CV3);
    float* R1 = (float*)(sm + G1_R1);
    float* R3 = (float*)(sm + G1_R3);

    const int tid = threadIdx.x, wid = tid >> 5, lane = tid & 31;
    const int gid = lane >> 2, tg = lane & 3;
    const int wm = wid >> 2, wn = wid & 3;

    if (tid < 128) {
        int r = m0 + tid;
        stok[tid] = g_tok[off + (r < cnt ? r : cnt - 1)];
    }
    __syncthreads();

    const int lrow = tid >> 2, lc = tid & 3;
    const __half* asrc = g_xh + (size_t)stok[lrow] * H_DIM + lc * 8;
    const uint32_t adst = (uint32_t)(lrow * 80 + lc * 16);
    const int kk0 = tid >> 5, nc0 = tid & 31;
    const int kk1 = (tid + 512) >> 5, nc1 = tid & 31;
    const float* b1s0 = W1 + (size_t)kk0 * F_DIM + n0 + nc0 * 4;
    const float* b1s1 = W1 + (size_t)kk1 * F_DIM + n0 + nc1 * 4;
    const float* b3s0 = W3 + (size_t)kk0 * F_DIM + n0 + nc0 * 4;
    const float* b3s1 = W3 + (size_t)kk1 * F_DIM + n0 + nc1 * 4;
    const uint32_t bd0 = (uint32_t)((kk0 * 128 + nc0 * 4) * 4);
    const uint32_t bd1 = (uint32_t)((kk1 * 128 + nc1 * 4) * 4);
    const uint32_t Ab = smem_u32(sm + G1_SA);
    const uint32_t R1b = smem_u32(R1), R3b = smem_u32(R3);
    const uint32_t CV1b = smem_u32(CV1), CV3b = smem_u32(CV3);

    // ldmatrix addresses
    uint32_t a_adr[2], b1_adr[2], b3_adr[2];
#pragma unroll
    for (int mt = 0; mt < 2; mt++) {
        int row = wm * 32 + mt * 16 + (lane & 15);
        a_adr[mt] = Ab + (uint32_t)(row * 80 + ((lane >> 4) & 1) * 16);
    }
#pragma unroll
    for (int np = 0; np < 2; np++) {
        int row = wn * 32 + np * 16 + (lane & 7) + ((lane >> 4) & 1) * 8;
        uint32_t o = (uint32_t)(row * 80 + ((lane >> 3) & 1) * 16);
        b1_adr[np] = CV1b + o;
        b3_adr[np] = CV3b + o;
    }

    float acc1[2][4][4] = {};
    float acc3[2][4][4] = {};

#define G1_ISSUE(c)                                         \
    do {                                                    \
        uint32_t _ao = ((c) & 1) * 10240u;                  \
        uint32_t _ro = ((c) & 1) * 16384u;                  \
        size_t _ka = (size_t)(c) * 32;                      \
        size_t _kb = (size_t)(c) * 32 * F_DIM;              \
        CPA(Ab + _ao + adst, asrc + _ka);                   \
        CPA(R1b + _ro + bd0, b1s0 + _kb);                   \
        CPA(R1b + _ro + bd1, b1s1 + _kb);                   \
        CPA(R3b + _ro + bd0, b3s0 + _kb);                   \
        CPA(R3b + _ro + bd1, b3s1 + _kb);                   \
        CPA_COMMIT();                                       \
    } while (0)

    G1_ISSUE(0);
    for (int c = 0; c < 32; c++) {
        const int b = c & 1;
        if (c + 1 < 32) { G1_ISSUE(c + 1); CPA_WAIT1(); }
        else CPA_WAIT0();
        __syncthreads();                 // raw(c)/A(c) ready; prior frag reads done
        cvt_tile(R1 + b * 4096, CV1, tid);
        cvt_tile(R3 + b * 4096, CV3, tid);
        __syncthreads();                 // conv ready
        const uint32_t ab_off = (uint32_t)b * 10240u;
#pragma unroll
        for (int ks = 0; ks < 2; ks++) {
            uint32_t a[2][4];
            LDSM4(a[0], a_adr[0] + ab_off + ks * 32);
            LDSM4(a[1], a_adr[1] + ab_off + ks * 32);
#pragma unroll
            for (int np = 0; np < 2; np++) {
                uint32_t f1[4], f3[4];
                LDSM4(f1, b1_adr[np] + ks * 32);
                LDSM4(f3, b3_adr[np] + ks * 32);
#pragma unroll
                for (int mt = 0; mt < 2; mt++) {
                    MMA_F16(acc1[mt][np * 2 + 0], a[mt], f1[0], f1[1]);
                    MMA_F16(acc1[mt][np * 2 + 1], a[mt], f1[2], f1[3]);
                    MMA_F16(acc3[mt][np * 2 + 0], a[mt], f3[0], f3[1]);
                    MMA_F16(acc3[mt][np * 2 + 1], a[mt], f3[2], f3[3]);
                }
            }
        }
        __syncthreads();                 // frag reads done before next cvt overwrite
    }

    // epilogue: silu(acc1)*acc3 -> g_h16 (fp16)
#pragma unroll
    for (int mt = 0; mt < 2; mt++) {
#pragma unroll
        for (int half = 0; half < 2; half++) {
            int row = m0 + wm * 32 + mt * 16 + half * 8 + gid;
            if (row < cnt) {
                __half* hp = g_h16 + (size_t)(off + row) * F_DIM + n0 + wn * 32 + tg * 2;
#pragma unroll
                for (int nt = 0; nt < 4; nt++) {
                    float g0 = acc1[mt][nt][half * 2 + 0];
                    float g1 = acc1[mt][nt][half * 2 + 1];
                    float u0 = acc3[mt][nt][half * 2 + 0];
                    float u1 = acc3[mt][nt][half * 2 + 1];
                    float o0 = u0 * (g0 / (1.0f + expf(-g0)));
                    float o1 = u1 * (g1 / (1.0f + expf(-g1)));
                    *(__half2*)(hp + nt * 8) = __floats2half2_rn(o0, o1);
                }
            }
        }
    }
}

// ================= GEMM2: out += coef * (h @ W2)  (split-K 4) =================
// tile M=128, N=128, Kc=32; 512 threads; 3-stage pipeline; 2 CTAs/SM; ldmatrix frags.
__global__ __launch_bounds__(512, 2) void gemm2_kernel(
    const float* __restrict__ w2, float* __restrict__ out) {
    const int z = blockIdx.z;
    const int e = z >> 2, ks4 = z & 3;
    const int cnt = g_cnt[e];
    const int m0 = blockIdx.y * 128;
    if (m0 >= cnt) return;
    const int off = g_off[e];
    const int n0 = blockIdx.x * 128;
    const int kbase = ks4 * (F_DIM / 4);
    const float* __restrict__ W2 = w2 + (size_t)e * F_DIM * H_DIM;

    extern __shared__ char sm[];
    int* srow = (int*)(sm + G2_ROW);
    uint32_t* CV = (uint32_t*)(sm + G2_CV);
    float* RB = (float*)(sm + G2_R);

    const int tid = threadIdx.x, wid = tid >> 5, lane = tid & 31;
    const int gid = lane >> 2, tg = lane & 3;
    const int wm = wid >> 2, wn = wid & 3;

    if (tid < 128) {
        int r = m0 + tid;
        srow[tid] = off + (r < cnt ? r : cnt - 1);
    }
    __syncthreads();

    const int lrow = tid >> 2, lc = tid & 3;
    const __half* asrc = g_h16 + (size_t)srow[lrow] * F_DIM + kbase + lc * 8;
    const uint32_t adst = (uint32_t)(lrow * 80 + lc * 16);
    const int kk0 = tid >> 5, nc0 = tid & 31;
    const int kk1 = (tid + 512) >> 5, nc1 = tid & 31;
    const float* bs0 = W2 + (size_t)(kbase + kk0) * H_DIM + n0 + nc0 * 4;
    const float* bs1 = W2 + (size_t)(kbase + kk1) * H_DIM + n0 + nc1 * 4;
    const uint32_t bd0 = (uint32_t)((kk0 * 128 + nc0 * 4) * 4);
    const uint32_t bd1 = (uint32_t)((kk1 * 128 + nc1 * 4) * 4);
    const uint32_t Ab = smem_u32(sm + G2_SA), Rb = smem_u32(RB);
    const uint32_t CVb = smem_u32(CV);

    uint32_t a_adr[2], b_adr[2];
#pragma unroll
    for (int mt = 0; mt < 2; mt++) {
        int row = wm * 32 + mt * 16 + (lane & 15);
        a_adr[mt] = Ab + (uint32_t)(row * 80 + ((lane >> 4) & 1) * 16);
    }
#pragma unroll
    for (int np = 0; np < 2; np++) {
        int row = wn * 32 + np * 16 + (lane & 7) + ((lane >> 4) & 1) * 8;
        b_adr[np] = CVb + (uint32_t)(row * 80 + ((lane >> 3) & 1) * 16);
    }

    float acc[2][4][4] = {};

#define G2_ISSUE(c)                                         \
    do {                                                    \
        uint32_t _s = (uint32_t)((c) % 3);                  \
        uint32_t _ao = _s * 10240u;                         \
        uint32_t _ro = _s * 16384u;                         \
        size_t _ka = (size_t)(c) * 32;                      \
        size_t _kb = (size_t)(c) * 32 * H_DIM;              \
        CPA(Ab + _ao + adst, asrc + _ka);                   \
        CPA(Rb + _ro + bd0, bs0 + _kb);                     \
        CPA(Rb + _ro + bd1, bs1 + _kb);                     \
        CPA_COMMIT();                                       \
    } while (0)

    G2_ISSUE(0);
    G2_ISSUE(1);
    for (int c = 0; c < 32; c++) {
        const int s = c % 3;
        if (c + 1 < 32) CPA_WAIT1();
        else CPA_WAIT0();
        __syncthreads();
        if (c + 2 < 32) G2_ISSUE(c + 2);
        cvt_tile(RB + s * 4096, CV, tid);
        __syncthreads();
        const uint32_t ab_off = (uint32_t)s * 10240u;
#pragma unroll
        for (int ks = 0; ks < 2; ks++) {
            uint32_t a[2][4];
            LDSM4(a[0], a_adr[0] + ab_off + ks * 32);
            LDSM4(a[1], a_adr[1] + ab_off + ks * 32);
#pragma unroll
            for (int np = 0; np < 2; np++) {
                uint32_t f[4];
                LDSM4(f, b_adr[np] + ks * 32);
#pragma unroll
                for (int mt = 0; mt < 2; mt++) {
                    MMA_F16(acc[mt][np * 2 + 0], a[mt], f[0], f[1]);
                    MMA_F16(acc[mt][np * 2 + 1], a[mt], f[2], f[3]);
                }
            }
        }
        // next iter's top sync orders frag reads vs cvt(c+1) writes
    }

    // epilogue: atomic scaled scatter
#pragma unroll
    for (int mt = 0; mt < 2; mt++) {
#pragma unroll
        for (int half = 0; half < 2; half++) {
            int row = m0 + wm * 32 + mt * 16 + half * 8 + gid;
            if (row < cnt) {
                int slot = off + row;
                int tok = g_tok[slot];
                float coef = g_coef[slot];
                float* dst = out + (size_t)tok * H_DIM + n0 + wn * 32 + tg * 2;
#pragma unroll
                for (int nt = 0; nt < 4; nt++) {
                    atomicAdd(dst + nt * 8 + 0, acc[mt][nt][half * 2 + 0] * coef);
                    atomicAdd(dst + nt * 8 + 1, acc[mt][nt][half * 2 + 1] * coef);
                }
            }
        }
    }
}

// ================= launch =================
extern "C" void kernel_launch(void* const* d_in, const int* in_sizes, int n_in,
                              void* d_out, int out_size) {
    const float* x  = (const float*)d_in[0];
    const float* gw = (const float*)d_in[1];
    const float* w1 = (const float*)d_in[2];
    const float* w3 = (const float*)d_in[3];
    const float* w2 = (const float*)d_in[4];
    float* out = (float*)d_out;
    float* out_logits = out + (size_t)T_TOK * H_DIM;

    cudaFuncSetAttribute(gemm1_kernel, cudaFuncAttributeMaxDynamicSharedMemorySize, G1_SMEM);
    cudaFuncSetAttribute(gemm2_kernel, cudaFuncAttributeMaxDynamicSharedMemorySize, G2_SMEM);

    router_kernel<<<T_TOK / 8, 256>>>(x, gw, out, out_logits);
    route_scatter_kernel<<<1, 1024>>>();
    gemm1_kernel<<<dim3(F_DIM / 128, T_TOK / 128, E_NUM), 512, G1_SMEM>>>(w1, w3);
    gemm2_kernel<<<dim3(H_DIM / 128, T_TOK / 128, E_NUM * 4), 512, G2_SMEM>>>(w2, out);
}

// round 13
// speedup vs baseline: 1.1021x; 1.0016x over previous
#include <cuda_runtime.h>
#include <cuda_fp16.h>
#include <math.h>
#include <math_constants.h>
#include <cstdint>

#define T_TOK 2048
#define H_DIM 1024
#define F_DIM 4096
#define E_NUM 8
#define MAXPAIRS (2 * T_TOK)

// ================= scratch (__device__ globals; no runtime alloc) =================
__device__ float  g_logits[T_TOK * E_NUM];
__device__ int    g_cnt[E_NUM];
__device__ int    g_off[E_NUM];
__device__ int    g_tok[MAXPAIRS];
__device__ float  g_coef[MAXPAIRS];
__device__ __align__(16) __half g_xh[T_TOK * H_DIM];                 // x in fp16
__device__ __align__(16) __half g_h16[(size_t)MAXPAIRS * F_DIM];     // intermediate, fp16

// ================= helpers =================
__device__ __forceinline__ uint32_t smem_u32(const void* p) {
    uint32_t a;
    asm("{ .reg .u64 t; cvta.to.shared.u64 t, %1; cvt.u32.u64 %0, t; }" : "=r"(a) : "l"(p));
    return a;
}
__device__ __forceinline__ uint32_t h2u(float a, float b) {
    __half2 h = __floats2half2_rn(a, b);
    return *reinterpret_cast<uint32_t*>(&h);
}
#define CPA(dst, src) \
    asm volatile("cp.async.cg.shared.global [%0], [%1], 16;" ::"r"(dst), "l"(src) : "memory")
#define CPA_COMMIT() asm volatile("cp.async.commit_group;" ::: "memory")
#define CPA_WAIT2()  asm volatile("cp.async.wait_group 2;" ::: "memory")
#define CPA_WAIT1()  asm volatile("cp.async.wait_group 1;" ::: "memory")
#define CPA_WAIT0()  asm volatile("cp.async.wait_group 0;" ::: "memory")
#define MMA_F16(d, a, b0, b1)                                                            \
    asm volatile(                                                                        \
        "mma.sync.aligned.m16n8k16.row.col.f32.f16.f16.f32 "                             \
        "{%0,%1,%2,%3},{%4,%5,%6,%7},{%8,%9},{%0,%1,%2,%3};"                             \
        : "+f"((d)[0]), "+f"((d)[1]), "+f"((d)[2]), "+f"((d)[3])                         \
        : "r"((a)[0]), "r"((a)[1]), "r"((a)[2]), "r"((a)[3]), "r"(b0), "r"(b1))
#define LDSM4(r, a)                                                                      \
    asm volatile("ldmatrix.sync.aligned.m8n8.x4.shared.b16 {%0,%1,%2,%3}, [%4];"          \
                 : "=r"((r)[0]), "=r"((r)[1]), "=r"((r)[2]), "=r"((r)[3]) : "r"(a))

// transpose-convert one 32k x 128n fp32 chunk (raw[k][n], row=128 floats) into
// fp16 [n][k] tile with row stride 20 words. 512 threads. Bank-conflict-free.
__device__ __forceinline__ void cvt_tile(const float* __restrict__ raw,
                                         uint32_t* __restrict__ conv, int tid) {
    const int n = tid & 127, kg = tid >> 7;          // kg in 0..3, 8 k's each
    const float* src = raw + kg * 8 * 128 + n;
    float f0 = src[0],       f1 = src[128],     f2 = src[2 * 128], f3 = src[3 * 128];
    float f4 = src[4 * 128], f5 = src[5 * 128], f6 = src[6 * 128], f7 = src[7 * 128];
    uint4 p;
    p.x = h2u(f0, f1); p.y = h2u(f2, f3); p.z = h2u(f4, f5); p.w = h2u(f6, f7);
    *(uint4*)(conv + n * 20 + kg * 4) = p;
}

// ================= K0: router logits + zero output rows + x->fp16 =================
__global__ __launch_bounds__(256) void router_kernel(
    const float* __restrict__ x, const float* __restrict__ gw,
    float* __restrict__ out, float* __restrict__ out_logits) {
    __shared__ float sgw[E_NUM * H_DIM];
    for (int i = threadIdx.x; i < H_DIM * E_NUM; i += 256) {
        int h = i >> 3, e = i & 7;
        sgw[e * H_DIM + h] = gw[i];
    }
    {
        float4 z = make_float4(0.f, 0.f, 0.f, 0.f);
        float4* dst = (float4*)(out + (size_t)blockIdx.x * 8 * H_DIM);
#pragma unroll
        for (int i = 0; i < 8; i++) dst[threadIdx.x + i * 256] = z;
    }
    {
        const float4* src = (const float4*)(x + (size_t)blockIdx.x * 8 * H_DIM);
        __half2* dst = (__half2*)(g_xh + (size_t)blockIdx.x * 8 * H_DIM);
#pragma unroll
        for (int i = 0; i < 8; i++) {
            float4 v = src[threadIdx.x + i * 256];
            dst[(threadIdx.x + i * 256) * 2 + 0] = __floats2half2_rn(v.x, v.y);
            dst[(threadIdx.x + i * 256) * 2 + 1] = __floats2half2_rn(v.z, v.w);
        }
    }
    __syncthreads();
    int warp = threadIdx.x >> 5, lane = threadIdx.x & 31;
    int t = blockIdx.x * 8 + warp;
    const float* xr = x + (size_t)t * H_DIM;
    float acc[E_NUM];
#pragma unroll
    for (int e = 0; e < E_NUM; e++) acc[e] = 0.0f;
    for (int h = lane; h < H_DIM; h += 32) {
        float xv = xr[h];
#pragma unroll
        for (int e = 0; e < E_NUM; e++) acc[e] += xv * sgw[e * H_DIM + h];
    }
#pragma unroll
    for (int e = 0; e < E_NUM; e++) {
#pragma unroll
        for (int o = 16; o > 0; o >>= 1) acc[e] += __shfl_down_sync(0xffffffffu, acc[e], o);
    }
    if (lane == 0) {
#pragma unroll
        for (int e = 0; e < E_NUM; e++) {
            g_logits[t * E_NUM + e] = acc[e];
            out_logits[t * E_NUM + e] = acc[e];
        }
    }
}

// ================= K1: routing + count + prefix + scatter (single CTA) =================
__global__ __launch_bounds__(1024) void route_scatter_kernel() {
    __shared__ int s_cnt[E_NUM];
    __shared__ int s_cur[E_NUM];
    const int tid = threadIdx.x;
    if (tid < E_NUM) s_cnt[tid] = 0;
    __syncthreads();
    int ti0[2], ti1[2];
    float tc0[2], tc1[2];
#pragma unroll
    for (int q = 0; q < 2; q++) {
        int t = tid + q * 1024;
        float s[E_NUM];
#pragma unroll
        for (int e = 0; e < E_NUM; e++) s[e] = g_logits[t * E_NUM + e];
        float mx = s[0];
        int i0 = 0;
#pragma unroll
        for (int e = 1; e < E_NUM; e++)
            if (s[e] > mx) { mx = s[e]; i0 = e; }
        float denom = 0.0f;
#pragma unroll
        for (int e = 0; e < E_NUM; e++) {
            float f = fmaxf(fabsf(s[e]), mx);
            if (!((mx - s[e]) / f > 0.02f)) denom += expf(s[e] - mx);
        }
        float w0 = 1.0f / denom;
        float mx2 = -CUDART_INF_F;
        int i1 = 0;
#pragma unroll
        for (int e = 0; e < E_NUM; e++)
            if (e != i0 && s[e] > mx2) { mx2 = s[e]; i1 = e; }
        float denom2 = 0.0f;
#pragma unroll
        for (int e = 0; e < E_NUM; e++) {
            if (e == i0) continue;
            float f = fmaxf(fabsf(s[e]), mx2);
            if (!((mx2 - s[e]) / f > 0.02f)) denom2 += expf(s[e] - mx2);
        }
        float w1v = 1.0f / denom2;
        float c0 = (i0 == 0) ? w0 : ((i1 == 0) ? w1v : 0.0f);
        float c1 = (i0 == 1) ? w0 : ((i1 == 1) ? w1v : 0.0f);
        ti0[q] = i0; tc0[q] = c0;
        ti1[q] = i1; tc1[q] = c1;
        if (c0 != 0.0f) atomicAdd(&s_cnt[i0], 1);
        if (c1 != 0.0f) atomicAdd(&s_cnt[i1], 1);
    }
    __syncthreads();
    if (tid == 0) {
        int acc = 0;
        for (int e = 0; e < E_NUM; e++) {
            g_off[e] = acc;
            s_cur[e] = acc;
            g_cnt[e] = s_cnt[e];
            acc += s_cnt[e];
        }
    }
    __syncthreads();
#pragma unroll
    for (int q = 0; q < 2; q++) {
        int t = tid + q * 1024;
        if (tc0[q] != 0.0f) {
            int slot = atomicAdd(&s_cur[ti0[q]], 1);
            g_tok[slot] = t; g_coef[slot] = tc0[q];
        }
        if (tc1[q] != 0.0f) {
            int slot = atomicAdd(&s_cur[ti1[q]], 1);
            g_tok[slot] = t; g_coef[slot] = tc1[q];
        }
    }
}

// ================= smem layouts =================
// Pipeline: A 4-ring (10240 B/stage), raw 3-ring (16384 B/stage), CV 2-ring (10240 B/buf)
#define TW 20
#define G1_TOK   0
#define G1_SA    512
#define G1_R1    (G1_SA + 4 * 10240)      // 41472
#define G1_R3    (G1_R1 + 3 * 16384)      // 90624
#define G1_CV1   (G1_R3 + 3 * 16384)      // 139776
#define G1_CV3   (G1_CV1 + 2 * 10240)     // 160256
#define G1_SMEM  (G1_CV3 + 2 * 10240)     // 180736 (176.5 KB, 1 CTA/SM)
#define G2_ROW   0
#define G2_SA    512
#define G2_R     (G2_SA + 4 * 10240)      // 41472
#define G2_CV    (G2_R + 3 * 16384)       // 90624
#define G2_SMEM  (G2_CV + 2 * 10240)      // 111104 (108.5 KB, 2 CTAs/SM)

// ================= GEMM1: h = silu(Xe@W1) * (Xe@W3) =================
// tile M=128, N=128, Kc=32; 512 threads (4x4 warps); ldmatrix frags;
// single-sync pipelined loop (cvt one chunk ahead, CV double-buffered).
__global__ __launch_bounds__(512) void gemm1_kernel(
    const float* __restrict__ w1, const float* __restrict__ w3) {
    const int e = blockIdx.z;
    const int cnt = g_cnt[e];
    const int m0 = blockIdx.y * 128;
    if (m0 >= cnt) return;
    const int off = g_off[e];
    const int n0 = blockIdx.x * 128;
    const float* __restrict__ W1 = w1 + (size_t)e * H_DIM * F_DIM;
    const float* __restrict__ W3 = w3 + (size_t)e * H_DIM * F_DIM;

    extern __shared__ char sm[];
    int* stok = (int*)(sm + G1_TOK);
    float* R1 = (float*)(sm + G1_R1);
    float* R3 = (float*)(sm + G1_R3);
    uint32_t* CV1 = (uint32_t*)(sm + G1_CV1);
    uint32_t* CV3 = (uint32_t*)(sm + G1_CV3);

    const int tid = threadIdx.x, wid = tid >> 5, lane = tid & 31;
    const int gid = lane >> 2, tg = lane & 3;
    const int wm = wid >> 2, wn = wid & 3;

    if (tid < 128) {
        int r = m0 + tid;
        stok[tid] = g_tok[off + (r < cnt ? r : cnt - 1)];
    }
    __syncthreads();

    const int lrow = tid >> 2, lc = tid & 3;
    const __half* asrc = g_xh + (size_t)stok[lrow] * H_DIM + lc * 8;
    const uint32_t adst = (uint32_t)(lrow * 80 + lc * 16);
    const int kk0 = tid >> 5, nc0 = tid & 31;
    const int kk1 = (tid + 512) >> 5, nc1 = tid & 31;
    const float* b1s0 = W1 + (size_t)kk0 * F_DIM + n0 + nc0 * 4;
    const float* b1s1 = W1 + (size_t)kk1 * F_DIM + n0 + nc1 * 4;
    const float* b3s0 = W3 + (size_t)kk0 * F_DIM + n0 + nc0 * 4;
    const float* b3s1 = W3 + (size_t)kk1 * F_DIM + n0 + nc1 * 4;
    const uint32_t bd0 = (uint32_t)((kk0 * 128 + nc0 * 4) * 4);
    const uint32_t bd1 = (uint32_t)((kk1 * 128 + nc1 * 4) * 4);
    const uint32_t Ab = smem_u32(sm + G1_SA);
    const uint32_t R1b = smem_u32(R1), R3b = smem_u32(R3);
    const uint32_t CV1b = smem_u32(CV1), CV3b = smem_u32(CV3);

    uint32_t a_adr[2], b1_adr[2], b3_adr[2];
#pragma unroll
    for (int mt = 0; mt < 2; mt++) {
        int row = wm * 32 + mt * 16 + (lane & 15);
        a_adr[mt] = Ab + (uint32_t)(row * 80 + ((lane >> 4) & 1) * 16);
    }
#pragma unroll
    for (int np = 0; np < 2; np++) {
        int row = wn * 32 + np * 16 + (lane & 7) + ((lane >> 4) & 1) * 8;
        uint32_t o = (uint32_t)(row * 80 + ((lane >> 3) & 1) * 16);
        b1_adr[np] = CV1b + o;
        b3_adr[np] = CV3b + o;
    }

    float acc1[2][4][4] = {};
    float acc3[2][4][4] = {};

#define G1_ISSUE(c)                                         \
    do {                                                    \
        uint32_t _ao = (uint32_t)((c) & 3) * 10240u;        \
        uint32_t _ro = (uint32_t)((c) % 3) * 16384u;        \
        size_t _ka = (size_t)(c) * 32;                      \
        size_t _kb = (size_t)(c) * 32 * F_DIM;              \
        CPA(Ab + _ao + adst, asrc + _ka);                   \
        CPA(R1b + _ro + bd0, b1s0 + _kb);                   \
        CPA(R1b + _ro + bd1, b1s1 + _kb);                   \
        CPA(R3b + _ro + bd0, b3s0 + _kb);                   \
        CPA(R3b + _ro + bd1, b3s1 + _kb);                   \
        CPA_COMMIT();                                       \
    } while (0)

    G1_ISSUE(0); G1_ISSUE(1); G1_ISSUE(2);
    CPA_WAIT2();
    __syncthreads();                      // raw(0) visible
    cvt_tile(R1, CV1, tid);               // cvt(0) -> CV buf 0
    cvt_tile(R3, CV3, tid);

    for (int c = 0; c < 32; c++) {
        // need group c+1 complete for cvt(c+1); WAIT1 only while group c+2 also in flight
        if (c + 2 < 32) CPA_WAIT1();
        else CPA_WAIT0();
        __syncthreads();                  // single barrier per chunk
        if (c + 3 < 32) G1_ISSUE(c + 3);
        if (c + 1 < 32) {                 // cvt one chunk ahead
            cvt_tile(R1 + ((c + 1) % 3) * 4096, CV1 + ((c + 1) & 1) * 2560, tid);
            cvt_tile(R3 + ((c + 1) % 3) * 4096, CV3 + ((c + 1) & 1) * 2560, tid);
        }
        const uint32_t ab_off = (uint32_t)(c & 3) * 10240u;
        const uint32_t cb_off = (uint32_t)(c & 1) * 10240u;
#pragma unroll
        for (int ks = 0; ks < 2; ks++) {
            uint32_t a[2][4];
            LDSM4(a[0], a_adr[0] + ab_off + ks * 32);
            LDSM4(a[1], a_adr[1] + ab_off + ks * 32);
#pragma unroll
            for (int np = 0; np < 2; np++) {
                uint32_t f1[4], f3[4];
                LDSM4(f1, b1_adr[np] + cb_off + ks * 32);
                LDSM4(f3, b3_adr[np] + cb_off + ks * 32);
#pragma unroll
                for (int mt = 0; mt < 2; mt++) {
                    MMA_F16(acc1[mt][np * 2 + 0], a[mt], f1[0], f1[1]);
                    MMA_F16(acc1[mt][np * 2 + 1], a[mt], f1[2], f1[3]);
                    MMA_F16(acc3[mt][np * 2 + 0], a[mt], f3[0], f3[1]);
                    MMA_F16(acc3[mt][np * 2 + 1], a[mt], f3[2], f3[3]);
                }
            }
        }
    }

    // epilogue: silu(acc1)*acc3 -> g_h16 (fp16)
#pragma unroll
    for (int mt = 0; mt < 2; mt++) {
#pragma unroll
        for (int half = 0; half < 2; half++) {
            int row = m0 + wm * 32 + mt * 16 + half * 8 + gid;
            if (row < cnt) {
                __half* hp = g_h16 + (size_t)(off + row) * F_DIM + n0 + wn * 32 + tg * 2;
#pragma unroll
                for (int nt = 0; nt < 4; nt++) {
                    float g0 = acc1[mt][nt][half * 2 + 0];
                    float g1 = acc1[mt][nt][half * 2 + 1];
                    float u0 = acc3[mt][nt][half * 2 + 0];
                    float u1 = acc3[mt][nt][half * 2 + 1];
                    float o0 = u0 * (g0 / (1.0f + expf(-g0)));
                    float o1 = u1 * (g1 / (1.0f + expf(-g1)));
                    *(__half2*)(hp + nt * 8) = __floats2half2_rn(o0, o1);
                }
            }
        }
    }
}

// ================= GEMM2: out += coef * (h @ W2)  (split-K 4) =================
// tile M=128, N=128, Kc=32; 512 threads; 2 CTAs/SM; single-sync pipelined loop.
__global__ __launch_bounds__(512, 2) void gemm2_kernel(
    const float* __restrict__ w2, float* __restrict__ out) {
    const int z = blockIdx.z;
    const int e = z >> 2, ks4 = z & 3;
    const int cnt = g_cnt[e];
    const int m0 = blockIdx.y * 128;
    if (m0 >= cnt) return;
    const int off = g_off[e];
    const int n0 = blockIdx.x * 128;
    const int kbase = ks4 * (F_DIM / 4);
    const float* __restrict__ W2 = w2 + (size_t)e * F_DIM * H_DIM;

    extern __shared__ char sm[];
    int* srow = (int*)(sm + G2_ROW);
    float* RB = (float*)(sm + G2_R);
    uint32_t* CV = (uint32_t*)(sm + G2_CV);

    const int tid = threadIdx.x, wid = tid >> 5, lane = tid & 31;
    const int gid = lane >> 2, tg = lane & 3;
    const int wm = wid >> 2, wn = wid & 3;

    if (tid < 128) {
        int r = m0 + tid;
        srow[tid] = off + (r < cnt ? r : cnt - 1);
    }
    __syncthreads();

    const int lrow = tid >> 2, lc = tid & 3;
    const __half* asrc = g_h16 + (size_t)srow[lrow] * F_DIM + kbase + lc * 8;
    const uint32_t adst = (uint32_t)(lrow * 80 + lc * 16);
    const int kk0 = tid >> 5, nc0 = tid & 31;
    const int kk1 = (tid + 512) >> 5, nc1 = tid & 31;
    const float* bs0 = W2 + (size_t)(kbase + kk0) * H_DIM + n0 + nc0 * 4;
    const float* bs1 = W2 + (size_t)(kbase + kk1) * H_DIM + n0 + nc1 * 4;
    const uint32_t bd0 = (uint32_t)((kk0 * 128 + nc0 * 4) * 4);
    const uint32_t bd1 = (uint32_t)((kk1 * 128 + nc1 * 4) * 4);
    const uint32_t Ab = smem_u32(sm + G2_SA), Rb = smem_u32(RB);
    const uint32_t CVb = smem_u32(CV);

    uint32_t a_adr[2], b_adr[2];
#pragma unroll
    for (int mt = 0; mt < 2; mt++) {
        int row = wm * 32 + mt * 16 + (lane & 15);
        a_adr[mt] = Ab + (uint32_t)(row * 80 + ((lane >> 4) & 1) * 16);
    }
#pragma unroll
    for (int np = 0; np < 2; np++) {
        int row = wn * 32 + np * 16 + (lane & 7) + ((lane >> 4) & 1) * 8;
        b_adr[np] = CVb + (uint32_t)(row * 80 + ((lane >> 3) & 1) * 16);
    }

    float acc[2][4][4] = {};

#define G2_ISSUE(c)                                         \
    do {                                                    \
        uint32_t _ao = (uint32_t)((c) & 3) * 10240u;        \
        uint32_t _ro = (uint32_t)((c) % 3) * 16384u;        \
        size_t _ka = (size_t)(c) * 32;                      \
        size_t _kb = (size_t)(c) * 32 * H_DIM;              \
        CPA(Ab + _ao + adst, asrc + _ka);                   \
        CPA(Rb + _ro + bd0, bs0 + _kb);                     \
        CPA(Rb + _ro + bd1, bs1 + _kb);                     \
        CPA_COMMIT();                                       \
    } while (0)

    G2_ISSUE(0); G2_ISSUE(1); G2_ISSUE(2);
    CPA_WAIT2();
    __syncthreads();
    cvt_tile(RB, CV, tid);                // cvt(0) -> CV buf 0

    for (int c = 0; c < 32; c++) {
        if (c + 2 < 32) CPA_WAIT1();      // group c+1 complete (cvt needs it)
        else CPA_WAIT0();
        __syncthreads();
        if (c + 3 < 32) G2_ISSUE(c + 3);
        if (c + 1 < 32)
            cvt_tile(RB + ((c + 1) % 3) * 4096, CV + ((c + 1) & 1) * 2560, tid);
        const uint32_t ab_off = (uint32_t)(c & 3) * 10240u;
        const uint32_t cb_off = (uint32_t)(c & 1) * 10240u;
#pragma unroll
        for (int ks = 0; ks < 2; ks++) {
            uint32_t a[2][4];
            LDSM4(a[0], a_adr[0] + ab_off + ks * 32);
            LDSM4(a[1], a_adr[1] + ab_off + ks * 32);
#pragma unroll
            for (int np = 0; np < 2; np++) {
                uint32_t f[4];
                LDSM4(f, b_adr[np] + cb_off + ks * 32);
#pragma unroll
                for (int mt = 0; mt < 2; mt++) {
                    MMA_F16(acc[mt][np * 2 + 0], a[mt], f[0], f[1]);
                    MMA_F16(acc[mt][np * 2 + 1], a[mt], f[2], f[3]);
                }
            }
        }
    }

    // epilogue: atomic scaled scatter
#pragma unroll
    for (int mt = 0; mt < 2; mt++) {
#pragma unroll
        for (int half = 0; half < 2; half++) {
            int row = m0 + wm * 32 + mt * 16 + half * 8 + gid;
            if (row < cnt) {
                int slot = off + row;
                int tok = g_tok[slot];
                float coef = g_coef[slot];
                float* dst = out + (size_t)tok * H_DIM + n0 + wn * 32 + tg * 2;
#pragma unroll
                for (int nt = 0; nt < 4; nt++) {
                    atomicAdd(dst + nt * 8 + 0, acc[mt][nt][half * 2 + 0] * coef);
                    atomicAdd(dst + nt * 8 + 1, acc[mt][nt][half * 2 + 1] * coef);
                }
            }
        }
    }
}

// ================= launch =================
extern "C" void kernel_launch(void* const* d_in, const int* in_sizes, int n_in,
                              void* d_out, int out_size) {
    const float* x  = (const float*)d_in[0];
    const float* gw = (const float*)d_in[1];
    const float* w1 = (const float*)d_in[2];
    const float* w3 = (const float*)d_in[3];
    const float* w2 = (const float*)d_in[4];
    float* out = (float*)d_out;
    float* out_logits = out + (size_t)T_TOK * H_DIM;

    cudaFuncSetAttribute(gemm1_kernel, cudaFuncAttributeMaxDynamicSharedMemorySize, G1_SMEM);
    cudaFuncSetAttribute(gemm2_kernel, cudaFuncAttributeMaxDynamicSharedMemorySize, G2_SMEM);

    router_kernel<<<T_TOK / 8, 256>>>(x, gw, out, out_logits);
    route_scatter_kernel<<<1, 1024>>>();
    gemm1_kernel<<<dim3(F_DIM / 128, T_TOK / 128, E_NUM), 512, G1_SMEM>>>(w1, w3);
    gemm2_kernel<<<dim3(H_DIM / 128, T_TOK / 128, E_NUM * 4), 512, G2_SMEM>>>(w2, out);
}